// round 4
// baseline (speedup 1.0000x reference)
#include <cuda_runtime.h>
#include <cuda_fp16.h>
#include <cstdint>
#include <cstddef>

// ---------------- problem constants ----------------
#define BT_N   4096      // B*T
#define F_DIM  256
#define GV     16384     // G*V
#define V_DIM  8192
#define DG     8
#define KK     768       // 3 * F_DIM  (fp16-split GEMM packed along K)

// ---------------- scratch (device globals; no runtime allocation) ----------------
__device__ float  g_hidden[(size_t)BT_N * GV];          // 256 MB fp32 logits
__device__ __half g_Asplit[(size_t)BT_N * KK];          // [xh | xh | xl]
__device__ __half g_Bsplit[(size_t)GV   * KK];          // [Wh | Wl | Wh]
__device__ float  g_R[BT_N * 2];                        // mask*inv_msum/Z per (bt,g)
__device__ float  g_MX[BT_N * 2];                       // row max of h per (bt,g)
__device__ float  g_marg[GV];                           // marginal accumulator
__device__ float  g_inv_msum;

// ---------------- accurate FFMA-based log (relative accuracy near 1) ----------------
__device__ __forceinline__ float my_logf(float a) {
    float m, r, s, t, i, f;
    int e;
    e = (__float_as_int(a) - 0x3f2aaaab) & 0xff800000;
    m = __int_as_float(__float_as_int(a) - e);
    i = (float)e * 1.19209290e-7f; // 2^-23
    f = m - 1.0f;
    s = f * f;
    r = -0.130310059f;
    t =  0.140869141f;
    r = fmaf(r, s, -0.121483512f);
    t = fmaf(t, s,  0.139814854f);
    r = fmaf(r, s, -0.166846126f);
    t = fmaf(t, s,  0.200120345f);
    r = fmaf(r, s, -0.249996200f);
    r = fmaf(t, f, r);
    r = fmaf(r, f,  0.333331972f);
    r = fmaf(r, f, -0.500000000f);
    r = fmaf(r, s, f);
    r = fmaf(i, 0.693147182f, r);
    return r;
}

__device__ __forceinline__ float my_expf(float a) {
    float f, r, j;
    int i;
    j = fmaf(1.442695041f, a, 12582912.f) - 12582912.f;
    f = fmaf(j, -6.93145752e-1f, a);
    f = fmaf(j, -1.42860677e-6f, f);
    i = (int)j;
    r = 1.37805939e-3f;
    r = fmaf(r, f, 8.37312452e-3f);
    r = fmaf(r, f, 4.16695364e-2f);
    r = fmaf(r, f, 1.66664720e-1f);
    r = fmaf(r, f, 4.99999851e-1f);
    r = fmaf(r, f, 1.00000000e+0f);
    r = fmaf(r, f, 1.00000000e+0f);
    r = __int_as_float(__float_as_int(r) + (i << 23));
    return r;
}

// ---------------- prep kernels ----------------
__global__ void prep_split_w(const float* __restrict__ W) {
    int idx = blockIdx.x * blockDim.x + threadIdx.x;
    if (idx >= GV * F_DIM) return;
    int n = idx >> 8, k = idx & 255;
    float w = W[idx];
    __half hi = __float2half_rn(w);
    __half lo = __float2half_rn(w - __half2float(hi));
    size_t base = (size_t)n * KK;
    g_Bsplit[base + k]        = hi;
    g_Bsplit[base + 256 + k]  = lo;
    g_Bsplit[base + 512 + k]  = hi;
}

__global__ void prep_split_x(const float* __restrict__ X) {
    int idx = blockIdx.x * blockDim.x + threadIdx.x;
    if (idx >= BT_N * F_DIM) return;
    int n = idx >> 8, k = idx & 255;
    float x = X[idx];
    __half hi = __float2half_rn(x);
    __half lo = __float2half_rn(x - __half2float(hi));
    size_t base = (size_t)n * KK;
    g_Asplit[base + k]        = hi;
    g_Asplit[base + 256 + k]  = hi;
    g_Asplit[base + 512 + k]  = lo;
}

__global__ void prep_misc(const int* __restrict__ mask) {
    int t = threadIdx.x;
    for (int i = t; i < GV; i += 256) g_marg[i] = 0.f;
    int s = 0;
    for (int i = t; i < BT_N; i += 256) s += mask[i];
    __shared__ int sm[256];
    sm[t] = s; __syncthreads();
    for (int o = 128; o; o >>= 1) { if (t < o) sm[t] += sm[t + o]; __syncthreads(); }
    if (t == 0) g_inv_msum = 1.0f / (float)sm[0];
}

// ---------------- GEMM: hidden = A' * B'^T + bias ----------------
// M=4096, N=16384, K=768 (fp16 split), block tile 128x256, warp tile 64x64,
// BK=64, 3-stage cp.async pipeline. 8 warps.
#define BM 128
#define BN 256
#define BK 64
#define STAGES 3
#define A_BYTES  (BM * BK * 2)          // 16384
#define B_BYTES  (BN * BK * 2)          // 32768
#define STG_BYTES (A_BYTES + B_BYTES)   // 49152
#define GEMM_SMEM (STAGES * STG_BYTES)  // 147456

__global__ void __launch_bounds__(256, 1) gemm_kernel(const float* __restrict__ bias) {
    extern __shared__ __align__(128) char smem[];
    int tid  = threadIdx.x;
    int lane = tid & 31, warp = tid >> 5;
    int wm = warp >> 2, wn = warp & 3;        // 2 x 4 warp grid, warp tile 64x64
    int bm = blockIdx.y, bn = blockIdx.x;
    const __half* gA = g_Asplit + (size_t)bm * BM * KK;
    const __half* gB = g_Bsplit + (size_t)bn * BN * KK;

    auto load_stage = [&](int s, int kt) {
        int k0 = kt * BK;
        char* sa = smem + s * STG_BYTES;
        char* sb = sa + A_BYTES;
        // A: 1024 16B-chunks (i = 0..3), B: 2048 chunks (i = 4..11)
        #pragma unroll
        for (int i = 0; i < 4; i++) {
            int idx = tid + 256 * i;
            int row = idx >> 3, c16 = idx & 7;
            int pc  = c16 ^ (row & 7);
            uint32_t d = (uint32_t)__cvta_generic_to_shared(sa + row * 128 + pc * 16);
            asm volatile("cp.async.cg.shared.global [%0], [%1], 16;\n"
                :: "r"(d), "l"(gA + (size_t)row * KK + k0 + c16 * 8));
        }
        #pragma unroll
        for (int i = 0; i < 8; i++) {
            int idx = tid + 256 * i;       // 0..2047
            int row = idx >> 3, c16 = idx & 7;
            int pc  = c16 ^ (row & 7);
            uint32_t d = (uint32_t)__cvta_generic_to_shared(sb + row * 128 + pc * 16);
            asm volatile("cp.async.cg.shared.global [%0], [%1], 16;\n"
                :: "r"(d), "l"(gB + (size_t)row * KK + k0 + c16 * 8));
        }
    };

    float acc[4][8][4];
    #pragma unroll
    for (int a = 0; a < 4; a++)
        #pragma unroll
        for (int b = 0; b < 8; b++)
            #pragma unroll
            for (int c = 0; c < 4; c++) acc[a][b][c] = 0.f;

    const int NKT = KK / BK;  // 12
    #pragma unroll
    for (int kt = 0; kt < STAGES - 1; kt++) {
        load_stage(kt, kt);
        asm volatile("cp.async.commit_group;\n");
    }

    #pragma unroll 1
    for (int kt = 0; kt < NKT; kt++) {
        asm volatile("cp.async.wait_group 1;\n");
        __syncthreads();
        int pf = kt + STAGES - 1;
        if (pf < NKT) load_stage(pf % STAGES, pf);
        asm volatile("cp.async.commit_group;\n");

        int s = kt % STAGES;
        const char* sa = smem + s * STG_BYTES;
        const char* sb = sa + A_BYTES;
        #pragma unroll
        for (int kk = 0; kk < 4; kk++) {  // 4 k16-steps within BK=64
            uint32_t a[4][4], b[8][2];
            int c16 = kk * 2 + (lane >> 4);
            #pragma unroll
            for (int mt = 0; mt < 4; mt++) {
                int row = wm * 64 + mt * 16 + (lane & 15);
                int pc  = c16 ^ (row & 7);
                uint32_t addr = (uint32_t)__cvta_generic_to_shared(sa + row * 128 + pc * 16);
                asm volatile("ldmatrix.sync.aligned.m8n8.x4.shared.b16 {%0,%1,%2,%3}, [%4];\n"
                    : "=r"(a[mt][0]), "=r"(a[mt][1]), "=r"(a[mt][2]), "=r"(a[mt][3]) : "r"(addr));
            }
            #pragma unroll
            for (int nb = 0; nb < 4; nb++) {
                int row = wn * 64 + nb * 16 + (lane & 15);
                int pc  = c16 ^ (row & 7);
                uint32_t addr = (uint32_t)__cvta_generic_to_shared(sb + row * 128 + pc * 16);
                uint32_t r0, r1, r2, r3;
                asm volatile("ldmatrix.sync.aligned.m8n8.x4.shared.b16 {%0,%1,%2,%3}, [%4];\n"
                    : "=r"(r0), "=r"(r1), "=r"(r2), "=r"(r3) : "r"(addr));
                b[nb * 2][0]     = r0; b[nb * 2 + 1][0] = r1;
                b[nb * 2][1]     = r2; b[nb * 2 + 1][1] = r3;
            }
            #pragma unroll
            for (int mt = 0; mt < 4; mt++)
                #pragma unroll
                for (int nt = 0; nt < 8; nt++) {
                    asm volatile("mma.sync.aligned.m16n8k16.row.col.f32.f16.f16.f32 "
                        "{%0,%1,%2,%3}, {%4,%5,%6,%7}, {%8,%9}, {%0,%1,%2,%3};\n"
                        : "+f"(acc[mt][nt][0]), "+f"(acc[mt][nt][1]),
                          "+f"(acc[mt][nt][2]), "+f"(acc[mt][nt][3])
                        : "r"(a[mt][0]), "r"(a[mt][1]), "r"(a[mt][2]), "r"(a[mt][3]),
                          "r"(b[nt][0]), "r"(b[nt][1]));
                }
        }
    }

    // epilogue: add bias, write fp32 hidden
    #pragma unroll
    for (int mt = 0; mt < 4; mt++) {
        int row0 = bm * BM + wm * 64 + mt * 16 + (lane >> 2);
        #pragma unroll
        for (int nt = 0; nt < 8; nt++) {
            int col = bn * BN + wn * 64 + nt * 8 + (lane & 3) * 2;
            float b0 = bias[col], b1 = bias[col + 1];
            float* p0 = g_hidden + (size_t)row0 * GV + col;
            float* p1 = g_hidden + (size_t)(row0 + 8) * GV + col;
            p0[0] = acc[mt][nt][0] + b0;
            p0[1] = acc[mt][nt][1] + b1;
            p1[0] = acc[mt][nt][2] + b0;
            p1[1] = acc[mt][nt][3] + b1;
        }
    }
}

// ---------------- row kernel: gumbel softmax + argmax + codevectors + soft-Z ----------------
__global__ void __launch_bounds__(256) row_kernel(
    const float* __restrict__ u, const float* __restrict__ emb,
    const int* __restrict__ mask, float* __restrict__ out)
{
    int r  = blockIdx.x;         // 0..8191 (= bt*2 + g)
    int bt = r >> 1, g = r & 1;
    int t  = threadIdx.x;
    const float* hrow = g_hidden + (size_t)bt * GV + (size_t)g * V_DIM;
    const float* urow = u + (size_t)r * V_DIM;
    const float* erow = emb + (size_t)g * V_DIM * DG;

    // thread t owns v in [t*32, t*32+32): vectorized loads
    float h[32], y[32];
    {
        const float4* h4 = (const float4*)(hrow + t * 32);
        const float4* u4 = (const float4*)(urow + t * 32);
        #pragma unroll
        for (int q = 0; q < 8; q++) {
            float4 hv = h4[q];
            float4 uv = u4[q];
            h[q * 4 + 0] = hv.x; h[q * 4 + 1] = hv.y; h[q * 4 + 2] = hv.z; h[q * 4 + 3] = hv.w;
            y[q * 4 + 0] = uv.x; y[q * 4 + 1] = uv.y; y[q * 4 + 2] = uv.z; y[q * 4 + 3] = uv.w;
        }
    }

    float mh = -1e30f, my = -1e30f;
    int   bi = 0;
    #pragma unroll
    for (int i = 0; i < 32; i++) {
        float uu = fmaxf(y[i], 1.17549435e-38f);
        float inner = -my_logf(uu);          // needs relative accuracy near u=1
        float gum   = -__logf(inner);        // absolute accuracy suffices -> MUFU
        float yv = h[i] + gum;
        y[i] = yv;
        mh = fmaxf(mh, h[i]);
        if (yv > my) { my = yv; bi = t * 32 + i; }
    }

    __shared__ float s1[256];
    __shared__ int   s2[256];

    // block max of h
    s1[t] = mh; __syncthreads();
    for (int o = 128; o; o >>= 1) { if (t < o) s1[t] = fmaxf(s1[t], s1[t + o]); __syncthreads(); }
    mh = s1[0]; __syncthreads();

    // block argmax of y (ties -> lower index)
    s1[t] = my; s2[t] = bi; __syncthreads();
    for (int o = 128; o; o >>= 1) {
        if (t < o) {
            float ov = s1[t + o]; int oi = s2[t + o];
            if (ov > s1[t] || (ov == s1[t] && oi < s2[t])) { s1[t] = ov; s2[t] = oi; }
        }
        __syncthreads();
    }
    my = s1[0];
    int amax = s2[0];
    __syncthreads();

    // exp sums
    float sh = 0.f, sy = 0.f;
    #pragma unroll
    for (int i = 0; i < 32; i++) {
        sh += __expf(h[i] - mh);
        float e = __expf(y[i] - my);
        y[i] = e; sy += e;
    }
    s1[t] = sh; __syncthreads();
    for (int o = 128; o; o >>= 1) { if (t < o) s1[t] += s1[t + o]; __syncthreads(); }
    sh = s1[0]; __syncthreads();
    s1[t] = sy; __syncthreads();
    for (int o = 128; o; o >>= 1) { if (t < o) s1[t] += s1[t + o]; __syncthreads(); }
    sy = s1[0]; __syncthreads();

    // codevectors: cv[d] = sum_v p_v * emb[v][d]  (v contiguous per thread)
    float cv[8] = {0,0,0,0,0,0,0,0};
    const float4* ep = (const float4*)(erow + (size_t)t * 32 * DG);
    #pragma unroll
    for (int i = 0; i < 32; i++) {
        float4 e0 = ep[i * 2], e1 = ep[i * 2 + 1];
        float p = y[i];
        cv[0] = fmaf(p, e0.x, cv[0]); cv[1] = fmaf(p, e0.y, cv[1]);
        cv[2] = fmaf(p, e0.z, cv[2]); cv[3] = fmaf(p, e0.w, cv[3]);
        cv[4] = fmaf(p, e1.x, cv[4]); cv[5] = fmaf(p, e1.y, cv[5]);
        cv[6] = fmaf(p, e1.z, cv[6]); cv[7] = fmaf(p, e1.w, cv[7]);
    }
    #pragma unroll
    for (int d = 0; d < 8; d++)
        for (int o = 16; o; o >>= 1) cv[d] += __shfl_xor_sync(0xffffffffu, cv[d], o);

    __shared__ float scv[8][8];
    int warp = t >> 5, lane = t & 31;
    if (lane == 0) {
        #pragma unroll
        for (int d = 0; d < 8; d++) scv[warp][d] = cv[d];
    }
    __syncthreads();
    if (t < 8) {
        float s = 0.f;
        #pragma unroll
        for (int w = 0; w < 8; w++) s += scv[w][t];
        out[bt * 16 + g * 8 + t] = s / sy;
    }
    if (t == 0) {
        out[65537 + r] = (float)amax;                              // targets_idx
        g_R[r]  = mask[bt] ? (g_inv_msum / sh) : 0.f;
        g_MX[r] = mh;
    }
}

// ---------------- marginal column reduction ----------------
__global__ void __launch_bounds__(256) marg_kernel() {
    int c = blockIdx.x * 256 + threadIdx.x;   // 0..16383
    int g = c >> 13;
    int bt0 = blockIdx.y * 256;
    float acc = 0.f;
    for (int bt = bt0; bt < bt0 + 256; ++bt) {
        int r = bt * 2 + g;
        acc += g_R[r] * __expf(g_hidden[(size_t)bt * GV + c] - g_MX[r]);
    }
    atomicAdd(&g_marg[c], acc);
}

// ---------------- perplexity ----------------
__global__ void __launch_bounds__(256) final_kernel(float* __restrict__ out) {
    int t = threadIdx.x;
    float s0 = 0.f, s1v = 0.f;
    for (int c = t; c < V_DIM; c += 256) {
        float m = g_marg[c];
        s0 += m * my_logf(m + 1e-7f);
    }
    for (int c = V_DIM + t; c < GV; c += 256) {
        float m = g_marg[c];
        s1v += m * my_logf(m + 1e-7f);
    }
    __shared__ float sa[256], sb[256];
    sa[t] = s0; sb[t] = s1v; __syncthreads();
    for (int o = 128; o; o >>= 1) {
        if (t < o) { sa[t] += sa[t + o]; sb[t] += sb[t + o]; }
        __syncthreads();
    }
    if (t == 0) out[65536] = my_expf(-sa[0]) + my_expf(-sb[0]);
}

// ---------------- launch ----------------
extern "C" void kernel_launch(void* const* d_in, const int* in_sizes, int n_in,
                              void* d_out, int out_size) {
    const float* x    = (const float*)d_in[0];   // [8,512,256]
    const float* u    = (const float*)d_in[1];   // [8192, 8192]
    const float* emb  = (const float*)d_in[2];   // [1, 16384, 8]
    const float* W    = (const float*)d_in[3];   // [16384, 256]
    const float* bias = (const float*)d_in[4];   // [16384]
    const int*   mask = (const int*)d_in[5];     // [8,512]
    float* out = (float*)d_out;

    cudaFuncSetAttribute(gemm_kernel, cudaFuncAttributeMaxDynamicSharedMemorySize, GEMM_SMEM);

    prep_split_w<<<(GV * F_DIM + 255) / 256, 256>>>(W);
    prep_split_x<<<(BT_N * F_DIM + 255) / 256, 256>>>(x);
    prep_misc<<<1, 256>>>(mask);

    dim3 ggrid(GV / BN, BT_N / BM);   // (64, 32)
    gemm_kernel<<<ggrid, 256, GEMM_SMEM>>>(bias);

    row_kernel<<<BT_N * 2, 256>>>(u, emb, mask, out);

    dim3 mgrid(GV / 256, 16);
    marg_kernel<<<mgrid, 256>>>();

    final_kernel<<<1, 256>>>(out);
}

// round 5
// speedup vs baseline: 1.6518x; 1.6518x over previous
#include <cuda_runtime.h>
#include <cuda_fp16.h>
#include <cstdint>
#include <cstddef>

// ---------------- problem constants ----------------
#define BT_N   4096      // B*T
#define F_DIM  256
#define GV     16384     // G*V
#define V_DIM  8192
#define DG     8
#define KK     768       // 3 * F_DIM  (fp16-split GEMM packed along K)

// ---------------- scratch (device globals; no runtime allocation) ----------------
__device__ float  g_hidden[(size_t)BT_N * GV];          // 256 MB fp32 logits
__device__ __half g_Asplit[(size_t)BT_N * KK];          // [xh | xh | xl]
__device__ __half g_Bsplit[(size_t)GV   * KK];          // [Wh | Wl | Wh]
__device__ float  g_R[BT_N * 2];                        // mask*inv_msum/Z per (bt,g)
__device__ float  g_MX[BT_N * 2];                       // row max of h per (bt,g)
__device__ float  g_marg[GV];                           // marginal accumulator
__device__ float  g_inv_msum;

// ---------------- accurate FFMA-based log (relative accuracy near 1) ----------------
__device__ __forceinline__ float my_logf(float a) {
    float m, r, s, t, i, f;
    int e;
    e = (__float_as_int(a) - 0x3f2aaaab) & 0xff800000;
    m = __int_as_float(__float_as_int(a) - e);
    i = (float)e * 1.19209290e-7f; // 2^-23
    f = m - 1.0f;
    s = f * f;
    r = -0.130310059f;
    t =  0.140869141f;
    r = fmaf(r, s, -0.121483512f);
    t = fmaf(t, s,  0.139814854f);
    r = fmaf(r, s, -0.166846126f);
    t = fmaf(t, s,  0.200120345f);
    r = fmaf(r, s, -0.249996200f);
    r = fmaf(t, f, r);
    r = fmaf(r, f,  0.333331972f);
    r = fmaf(r, f, -0.500000000f);
    r = fmaf(r, s, f);
    r = fmaf(i, 0.693147182f, r);
    return r;
}

__device__ __forceinline__ float my_expf(float a) {
    float f, r, j;
    int i;
    j = fmaf(1.442695041f, a, 12582912.f) - 12582912.f;
    f = fmaf(j, -6.93145752e-1f, a);
    f = fmaf(j, -1.42860677e-6f, f);
    i = (int)j;
    r = 1.37805939e-3f;
    r = fmaf(r, f, 8.37312452e-3f);
    r = fmaf(r, f, 4.16695364e-2f);
    r = fmaf(r, f, 1.66664720e-1f);
    r = fmaf(r, f, 4.99999851e-1f);
    r = fmaf(r, f, 1.00000000e+0f);
    r = fmaf(r, f, 1.00000000e+0f);
    r = __int_as_float(__float_as_int(r) + (i << 23));
    return r;
}

// ---------------- prep kernels ----------------
__global__ void prep_split_w(const float* __restrict__ W) {
    int idx = blockIdx.x * blockDim.x + threadIdx.x;
    if (idx >= GV * F_DIM) return;
    int n = idx >> 8, k = idx & 255;
    float w = W[idx];
    __half hi = __float2half_rn(w);
    __half lo = __float2half_rn(w - __half2float(hi));
    size_t base = (size_t)n * KK;
    g_Bsplit[base + k]        = hi;
    g_Bsplit[base + 256 + k]  = lo;
    g_Bsplit[base + 512 + k]  = hi;
}

__global__ void prep_split_x(const float* __restrict__ X) {
    int idx = blockIdx.x * blockDim.x + threadIdx.x;
    if (idx >= BT_N * F_DIM) return;
    int n = idx >> 8, k = idx & 255;
    float x = X[idx];
    __half hi = __float2half_rn(x);
    __half lo = __float2half_rn(x - __half2float(hi));
    size_t base = (size_t)n * KK;
    g_Asplit[base + k]        = hi;
    g_Asplit[base + 256 + k]  = hi;
    g_Asplit[base + 512 + k]  = lo;
}

__global__ void prep_misc(const int* __restrict__ mask) {
    int t = threadIdx.x;
    for (int i = t; i < GV; i += 256) g_marg[i] = 0.f;
    int s = 0;
    for (int i = t; i < BT_N; i += 256) s += mask[i];
    __shared__ int sm[256];
    sm[t] = s; __syncthreads();
    for (int o = 128; o; o >>= 1) { if (t < o) sm[t] += sm[t + o]; __syncthreads(); }
    if (t == 0) g_inv_msum = 1.0f / (float)sm[0];
}

// ---------------- GEMM: hidden = A' * B'^T + bias ----------------
// M=4096, N=16384, K=768 (fp16 split).
// Block tile 128x128, 4 warps (128 threads), warp tile 64x64, BK=64, 3 stages.
// 2 CTAs/SM co-residency is the point: sync/memory stalls of one CTA hide
// behind the other's HMMA stream.
#define BM 128
#define BN 128
#define BK 64
#define STAGES 3
#define A_BYTES  (BM * BK * 2)          // 16384
#define STG_BYTES (2 * A_BYTES)         // 32768
#define GEMM_SMEM (STAGES * STG_BYTES)  // 98304

__global__ void __launch_bounds__(128, 2) gemm_kernel(const float* __restrict__ bias) {
    extern __shared__ __align__(128) char smem[];
    int tid  = threadIdx.x;
    int lane = tid & 31, warp = tid >> 5;
    int wm = warp >> 1, wn = warp & 1;        // 2 x 2 warp grid, warp tile 64x64
    int bm = blockIdx.y, bn = blockIdx.x;
    const __half* gA = g_Asplit + (size_t)bm * BM * KK;
    const __half* gB = g_Bsplit + (size_t)bn * BN * KK;

    auto load_stage = [&](int s, int kt) {
        int k0 = kt * BK;
        char* sa = smem + s * STG_BYTES;
        char* sb = sa + A_BYTES;
        #pragma unroll
        for (int i = 0; i < 8; i++) {
            int idx = tid + 128 * i;       // 0..1023
            int row = idx >> 3, c16 = idx & 7;
            int pc  = c16 ^ (row & 7);
            uint32_t da = (uint32_t)__cvta_generic_to_shared(sa + row * 128 + pc * 16);
            asm volatile("cp.async.cg.shared.global [%0], [%1], 16;\n"
                :: "r"(da), "l"(gA + (size_t)row * KK + k0 + c16 * 8));
            uint32_t db = (uint32_t)__cvta_generic_to_shared(sb + row * 128 + pc * 16);
            asm volatile("cp.async.cg.shared.global [%0], [%1], 16;\n"
                :: "r"(db), "l"(gB + (size_t)row * KK + k0 + c16 * 8));
        }
    };

    float acc[4][8][4];
    #pragma unroll
    for (int a = 0; a < 4; a++)
        #pragma unroll
        for (int b = 0; b < 8; b++)
            #pragma unroll
            for (int c = 0; c < 4; c++) acc[a][b][c] = 0.f;

    const int NKT = KK / BK;  // 12
    #pragma unroll
    for (int kt = 0; kt < STAGES - 1; kt++) {
        load_stage(kt, kt);
        asm volatile("cp.async.commit_group;\n");
    }

    #pragma unroll 1
    for (int kt = 0; kt < NKT; kt++) {
        asm volatile("cp.async.wait_group 1;\n");
        __syncthreads();
        int pf = kt + STAGES - 1;
        if (pf < NKT) load_stage(pf % STAGES, pf);
        asm volatile("cp.async.commit_group;\n");

        int s = kt % STAGES;
        const char* sa = smem + s * STG_BYTES;
        const char* sb = sa + A_BYTES;
        #pragma unroll
        for (int kk = 0; kk < 4; kk++) {  // 4 k16-steps within BK=64
            uint32_t a[4][4], b[8][2];
            int c16 = kk * 2 + (lane >> 4);
            #pragma unroll
            for (int mt = 0; mt < 4; mt++) {
                int row = wm * 64 + mt * 16 + (lane & 15);
                int pc  = c16 ^ (row & 7);
                uint32_t addr = (uint32_t)__cvta_generic_to_shared(sa + row * 128 + pc * 16);
                asm volatile("ldmatrix.sync.aligned.m8n8.x4.shared.b16 {%0,%1,%2,%3}, [%4];\n"
                    : "=r"(a[mt][0]), "=r"(a[mt][1]), "=r"(a[mt][2]), "=r"(a[mt][3]) : "r"(addr));
            }
            #pragma unroll
            for (int nb = 0; nb < 4; nb++) {
                int row = wn * 64 + nb * 16 + (lane & 15);
                int pc  = c16 ^ (row & 7);
                uint32_t addr = (uint32_t)__cvta_generic_to_shared(sb + row * 128 + pc * 16);
                uint32_t r0, r1, r2, r3;
                asm volatile("ldmatrix.sync.aligned.m8n8.x4.shared.b16 {%0,%1,%2,%3}, [%4];\n"
                    : "=r"(r0), "=r"(r1), "=r"(r2), "=r"(r3) : "r"(addr));
                b[nb * 2][0]     = r0; b[nb * 2 + 1][0] = r1;
                b[nb * 2][1]     = r2; b[nb * 2 + 1][1] = r3;
            }
            #pragma unroll
            for (int mt = 0; mt < 4; mt++)
                #pragma unroll
                for (int nt = 0; nt < 8; nt++) {
                    asm volatile("mma.sync.aligned.m16n8k16.row.col.f32.f16.f16.f32 "
                        "{%0,%1,%2,%3}, {%4,%5,%6,%7}, {%8,%9}, {%0,%1,%2,%3};\n"
                        : "+f"(acc[mt][nt][0]), "+f"(acc[mt][nt][1]),
                          "+f"(acc[mt][nt][2]), "+f"(acc[mt][nt][3])
                        : "r"(a[mt][0]), "r"(a[mt][1]), "r"(a[mt][2]), "r"(a[mt][3]),
                          "r"(b[nt][0]), "r"(b[nt][1]));
                }
        }
    }

    // epilogue: add bias, write fp32 hidden
    #pragma unroll
    for (int mt = 0; mt < 4; mt++) {
        int row0 = bm * BM + wm * 64 + mt * 16 + (lane >> 2);
        #pragma unroll
        for (int nt = 0; nt < 8; nt++) {
            int col = bn * BN + wn * 64 + nt * 8 + (lane & 3) * 2;
            float b0 = bias[col], b1 = bias[col + 1];
            float* p0 = g_hidden + (size_t)row0 * GV + col;
            float* p1 = g_hidden + (size_t)(row0 + 8) * GV + col;
            p0[0] = acc[mt][nt][0] + b0;
            p0[1] = acc[mt][nt][1] + b1;
            p1[0] = acc[mt][nt][2] + b0;
            p1[1] = acc[mt][nt][3] + b1;
        }
    }
}

// ---------------- row kernel: gumbel softmax + argmax + codevectors + soft-Z ----------------
// Warp-coalesced access (v = i*256 + t). MUFU for outer gumbel log + all exps;
// FFMA polynomial only for the inner log (relative accuracy near u=1 decides argmax).
__global__ void __launch_bounds__(256) row_kernel(
    const float* __restrict__ u, const float* __restrict__ emb,
    const int* __restrict__ mask, float* __restrict__ out)
{
    int r  = blockIdx.x;         // 0..8191 (= bt*2 + g)
    int bt = r >> 1, g = r & 1;
    int t  = threadIdx.x;
    const float* hrow = g_hidden + (size_t)bt * GV + (size_t)g * V_DIM;
    const float* urow = u + (size_t)r * V_DIM;
    const float* erow = emb + (size_t)g * V_DIM * DG;

    float h[32], y[32];
    float mh = -1e30f, my = -1e30f;
    int   bi = 0;
    #pragma unroll
    for (int i = 0; i < 32; i++) {
        int v = i * 256 + t;
        float hv = hrow[v];
        float uu = fmaxf(urow[v], 1.17549435e-38f);
        float inner = -my_logf(uu);          // needs relative accuracy near u=1
        float gum   = -__logf(inner);        // absolute accuracy suffices -> MUFU
        float yv = hv + gum;
        h[i] = hv; y[i] = yv;
        mh = fmaxf(mh, hv);
        if (yv > my) { my = yv; bi = v; }
    }

    __shared__ float s1[256];
    __shared__ int   s2[256];

    // block max of h
    s1[t] = mh; __syncthreads();
    for (int o = 128; o; o >>= 1) { if (t < o) s1[t] = fmaxf(s1[t], s1[t + o]); __syncthreads(); }
    mh = s1[0]; __syncthreads();

    // block argmax of y (ties -> lower index)
    s1[t] = my; s2[t] = bi; __syncthreads();
    for (int o = 128; o; o >>= 1) {
        if (t < o) {
            float ov = s1[t + o]; int oi = s2[t + o];
            if (ov > s1[t] || (ov == s1[t] && oi < s2[t])) { s1[t] = ov; s2[t] = oi; }
        }
        __syncthreads();
    }
    my = s1[0];
    int amax = s2[0];
    __syncthreads();

    // exp sums
    float sh = 0.f, sy = 0.f;
    #pragma unroll
    for (int i = 0; i < 32; i++) {
        sh += __expf(h[i] - mh);
        float e = __expf(y[i] - my);
        y[i] = e; sy += e;
    }
    s1[t] = sh; __syncthreads();
    for (int o = 128; o; o >>= 1) { if (t < o) s1[t] += s1[t + o]; __syncthreads(); }
    sh = s1[0]; __syncthreads();
    s1[t] = sy; __syncthreads();
    for (int o = 128; o; o >>= 1) { if (t < o) s1[t] += s1[t + o]; __syncthreads(); }
    sy = s1[0]; __syncthreads();

    // codevectors: cv[d] = sum_v p_v * emb[v][d]
    float cv[8] = {0,0,0,0,0,0,0,0};
    #pragma unroll
    for (int i = 0; i < 32; i++) {
        int v = i * 256 + t;
        const float4* ep = (const float4*)(erow + (size_t)v * DG);
        float4 e0 = ep[0], e1 = ep[1];
        float p = y[i];
        cv[0] = fmaf(p, e0.x, cv[0]); cv[1] = fmaf(p, e0.y, cv[1]);
        cv[2] = fmaf(p, e0.z, cv[2]); cv[3] = fmaf(p, e0.w, cv[3]);
        cv[4] = fmaf(p, e1.x, cv[4]); cv[5] = fmaf(p, e1.y, cv[5]);
        cv[6] = fmaf(p, e1.z, cv[6]); cv[7] = fmaf(p, e1.w, cv[7]);
    }
    #pragma unroll
    for (int d = 0; d < 8; d++)
        for (int o = 16; o; o >>= 1) cv[d] += __shfl_xor_sync(0xffffffffu, cv[d], o);

    __shared__ float scv[8][8];
    int warp = t >> 5, lane = t & 31;
    if (lane == 0) {
        #pragma unroll
        for (int d = 0; d < 8; d++) scv[warp][d] = cv[d];
    }
    __syncthreads();
    if (t < 8) {
        float s = 0.f;
        #pragma unroll
        for (int w = 0; w < 8; w++) s += scv[w][t];
        out[bt * 16 + g * 8 + t] = s / sy;
    }
    if (t == 0) {
        out[65537 + r] = (float)amax;                              // targets_idx
        g_R[r]  = mask[bt] ? (g_inv_msum / sh) : 0.f;
        g_MX[r] = mh;
    }
}

// ---------------- marginal column reduction ----------------
__global__ void __launch_bounds__(256) marg_kernel() {
    int c = blockIdx.x * 256 + threadIdx.x;   // 0..16383
    int g = c >> 13;
    int bt0 = blockIdx.y * 256;
    float acc = 0.f;
    for (int bt = bt0; bt < bt0 + 256; ++bt) {
        int r = bt * 2 + g;
        acc += g_R[r] * __expf(g_hidden[(size_t)bt * GV + c] - g_MX[r]);
    }
    atomicAdd(&g_marg[c], acc);
}

// ---------------- perplexity ----------------
__global__ void __launch_bounds__(256) final_kernel(float* __restrict__ out) {
    int t = threadIdx.x;
    float s0 = 0.f, s1v = 0.f;
    for (int c = t; c < V_DIM; c += 256) {
        float m = g_marg[c];
        s0 += m * my_logf(m + 1e-7f);
    }
    for (int c = V_DIM + t; c < GV; c += 256) {
        float m = g_marg[c];
        s1v += m * my_logf(m + 1e-7f);
    }
    __shared__ float sa[256], sb[256];
    sa[t] = s0; sb[t] = s1v; __syncthreads();
    for (int o = 128; o; o >>= 1) {
        if (t < o) { sa[t] += sa[t + o]; sb[t] += sb[t + o]; }
        __syncthreads();
    }
    if (t == 0) out[65536] = my_expf(-sa[0]) + my_expf(-sb[0]);
}

// ---------------- launch ----------------
extern "C" void kernel_launch(void* const* d_in, const int* in_sizes, int n_in,
                              void* d_out, int out_size) {
    const float* x    = (const float*)d_in[0];   // [8,512,256]
    const float* u    = (const float*)d_in[1];   // [8192, 8192]
    const float* emb  = (const float*)d_in[2];   // [1, 16384, 8]
    const float* W    = (const float*)d_in[3];   // [16384, 256]
    const float* bias = (const float*)d_in[4];   // [16384]
    const int*   mask = (const int*)d_in[5];     // [8,512]
    float* out = (float*)d_out;

    cudaFuncSetAttribute(gemm_kernel, cudaFuncAttributeMaxDynamicSharedMemorySize, GEMM_SMEM);

    prep_split_w<<<(GV * F_DIM + 255) / 256, 256>>>(W);
    prep_split_x<<<(BT_N * F_DIM + 255) / 256, 256>>>(x);
    prep_misc<<<1, 256>>>(mask);

    dim3 ggrid(GV / BN, BT_N / BM);   // (128, 32)
    gemm_kernel<<<ggrid, 128, GEMM_SMEM>>>(bias);

    row_kernel<<<BT_N * 2, 256>>>(u, emb, mask, out);

    dim3 mgrid(GV / 256, 16);
    marg_kernel<<<mgrid, 256>>>();

    final_kernel<<<1, 256>>>(out);
}

// round 6
// speedup vs baseline: 1.7742x; 1.0741x over previous
#include <cuda_runtime.h>
#include <cuda_fp16.h>
#include <cstdint>
#include <cstddef>

// ---------------- problem constants ----------------
#define BT_N   4096      // B*T
#define F_DIM  256
#define GV     16384     // G*V
#define V_DIM  8192
#define DG     8
#define KK     768       // 3 * F_DIM  (fp16-split GEMM packed along K)

// ---------------- scratch (device globals; no runtime allocation) ----------------
__device__ float  g_hidden[(size_t)BT_N * GV];          // 256 MB fp32 logits
__device__ __half g_Asplit[(size_t)BT_N * KK];          // [xh | xh | xl]
__device__ __half g_Bsplit[(size_t)GV   * KK];          // [Wh | Wl | Wh]
__device__ float  g_R[BT_N * 2];                        // mask*inv_msum/Z per (bt,g)
__device__ float  g_MX[BT_N * 2];                       // row max of h per (bt,g)
__device__ float  g_marg[GV];                           // marginal accumulator
__device__ float  g_inv_msum;

// ---------------- accurate FFMA-based log (relative accuracy everywhere) ----------------
__device__ __forceinline__ float my_logf(float a) {
    float m, r, s, t, i, f;
    int e;
    e = (__float_as_int(a) - 0x3f2aaaab) & 0xff800000;
    m = __int_as_float(__float_as_int(a) - e);
    i = (float)e * 1.19209290e-7f; // 2^-23
    f = m - 1.0f;
    s = f * f;
    r = -0.130310059f;
    t =  0.140869141f;
    r = fmaf(r, s, -0.121483512f);
    t = fmaf(t, s,  0.139814854f);
    r = fmaf(r, s, -0.166846126f);
    t = fmaf(t, s,  0.200120345f);
    r = fmaf(r, s, -0.249996200f);
    r = fmaf(t, f, r);
    r = fmaf(r, f,  0.333331972f);
    r = fmaf(r, f, -0.500000000f);
    r = fmaf(r, s, f);
    r = fmaf(i, 0.693147182f, r);
    return r;
}

__device__ __forceinline__ float my_expf(float a) {
    float f, r, j;
    int i;
    j = fmaf(1.442695041f, a, 12582912.f) - 12582912.f;
    f = fmaf(j, -6.93145752e-1f, a);
    f = fmaf(j, -1.42860677e-6f, f);
    i = (int)j;
    r = 1.37805939e-3f;
    r = fmaf(r, f, 8.37312452e-3f);
    r = fmaf(r, f, 4.16695364e-2f);
    r = fmaf(r, f, 1.66664720e-1f);
    r = fmaf(r, f, 4.99999851e-1f);
    r = fmaf(r, f, 1.00000000e+0f);
    r = fmaf(r, f, 1.00000000e+0f);
    r = __int_as_float(__float_as_int(r) + (i << 23));
    return r;
}

// ---------------- prep kernels ----------------
__global__ void prep_split_w(const float* __restrict__ W) {
    int idx = blockIdx.x * blockDim.x + threadIdx.x;
    if (idx >= GV * F_DIM) return;
    int n = idx >> 8, k = idx & 255;
    float w = W[idx];
    __half hi = __float2half_rn(w);
    __half lo = __float2half_rn(w - __half2float(hi));
    size_t base = (size_t)n * KK;
    g_Bsplit[base + k]        = hi;
    g_Bsplit[base + 256 + k]  = lo;
    g_Bsplit[base + 512 + k]  = hi;
}

__global__ void prep_split_x(const float* __restrict__ X) {
    int idx = blockIdx.x * blockDim.x + threadIdx.x;
    if (idx >= BT_N * F_DIM) return;
    int n = idx >> 8, k = idx & 255;
    float x = X[idx];
    __half hi = __float2half_rn(x);
    __half lo = __float2half_rn(x - __half2float(hi));
    size_t base = (size_t)n * KK;
    g_Asplit[base + k]        = hi;
    g_Asplit[base + 256 + k]  = hi;
    g_Asplit[base + 512 + k]  = lo;
}

__global__ void prep_misc(const int* __restrict__ mask) {
    int t = threadIdx.x;
    for (int i = t; i < GV; i += 256) g_marg[i] = 0.f;
    int s = 0;
    for (int i = t; i < BT_N; i += 256) s += mask[i];
    __shared__ int sm[256];
    sm[t] = s; __syncthreads();
    for (int o = 128; o; o >>= 1) { if (t < o) sm[t] += sm[t + o]; __syncthreads(); }
    if (t == 0) g_inv_msum = 1.0f / (float)sm[0];
}

// ---------------- GEMM: hidden = A' * B'^T + bias ----------------
// Block tile 128x128, 4 warps, warp tile 64x64, BK=64, 3 stages, 2 CTAs/SM.
// Register fragment double-buffering across the 4 k16-steps of each stage.
#define BM 128
#define BN 128
#define BK 64
#define STAGES 3
#define A_BYTES  (BM * BK * 2)          // 16384
#define STG_BYTES (2 * A_BYTES)         // 32768
#define GEMM_SMEM (STAGES * STG_BYTES)  // 98304

__global__ void __launch_bounds__(128, 2) gemm_kernel(const float* __restrict__ bias) {
    extern __shared__ __align__(128) char smem[];
    int tid  = threadIdx.x;
    int lane = tid & 31, warp = tid >> 5;
    int wm = warp >> 1, wn = warp & 1;        // 2 x 2 warp grid, warp tile 64x64
    int bm = blockIdx.y, bn = blockIdx.x;
    const __half* gA = g_Asplit + (size_t)bm * BM * KK;
    const __half* gB = g_Bsplit + (size_t)bn * BN * KK;

    auto load_stage = [&](int s, int kt) {
        int k0 = kt * BK;
        char* sa = smem + s * STG_BYTES;
        char* sb = sa + A_BYTES;
        #pragma unroll
        for (int i = 0; i < 8; i++) {
            int idx = tid + 128 * i;       // 0..1023
            int row = idx >> 3, c16 = idx & 7;
            int pc  = c16 ^ (row & 7);
            uint32_t da = (uint32_t)__cvta_generic_to_shared(sa + row * 128 + pc * 16);
            asm volatile("cp.async.cg.shared.global [%0], [%1], 16;\n"
                :: "r"(da), "l"(gA + (size_t)row * KK + k0 + c16 * 8));
            uint32_t db = (uint32_t)__cvta_generic_to_shared(sb + row * 128 + pc * 16);
            asm volatile("cp.async.cg.shared.global [%0], [%1], 16;\n"
                :: "r"(db), "l"(gB + (size_t)row * KK + k0 + c16 * 8));
        }
    };

    float acc[4][8][4];
    #pragma unroll
    for (int a = 0; a < 4; a++)
        #pragma unroll
        for (int b = 0; b < 8; b++)
            #pragma unroll
            for (int c = 0; c < 4; c++) acc[a][b][c] = 0.f;

    const int NKT = KK / BK;  // 12
    #pragma unroll
    for (int kt = 0; kt < STAGES - 1; kt++) {
        load_stage(kt, kt);
        asm volatile("cp.async.commit_group;\n");
    }

    uint32_t afrag[2][4][4], bfrag[2][8][2];

    #pragma unroll 1
    for (int kt = 0; kt < NKT; kt++) {
        asm volatile("cp.async.wait_group 1;\n");
        __syncthreads();
        int pf = kt + STAGES - 1;
        if (pf < NKT) load_stage(pf % STAGES, pf);
        asm volatile("cp.async.commit_group;\n");

        int s = kt % STAGES;
        const char* sa = smem + s * STG_BYTES;
        const char* sb = sa + A_BYTES;

        auto load_frag = [&](int kk, uint32_t a[4][4], uint32_t b[8][2]) {
            int c16 = kk * 2 + (lane >> 4);
            #pragma unroll
            for (int mt = 0; mt < 4; mt++) {
                int row = wm * 64 + mt * 16 + (lane & 15);
                int pc  = c16 ^ (row & 7);
                uint32_t addr = (uint32_t)__cvta_generic_to_shared(sa + row * 128 + pc * 16);
                asm volatile("ldmatrix.sync.aligned.m8n8.x4.shared.b16 {%0,%1,%2,%3}, [%4];\n"
                    : "=r"(a[mt][0]), "=r"(a[mt][1]), "=r"(a[mt][2]), "=r"(a[mt][3]) : "r"(addr));
            }
            #pragma unroll
            for (int nb = 0; nb < 4; nb++) {
                int row = wn * 64 + nb * 16 + (lane & 15);
                int pc  = c16 ^ (row & 7);
                uint32_t addr = (uint32_t)__cvta_generic_to_shared(sb + row * 128 + pc * 16);
                uint32_t r0, r1, r2, r3;
                asm volatile("ldmatrix.sync.aligned.m8n8.x4.shared.b16 {%0,%1,%2,%3}, [%4];\n"
                    : "=r"(r0), "=r"(r1), "=r"(r2), "=r"(r3) : "r"(addr));
                b[nb * 2][0]     = r0; b[nb * 2 + 1][0] = r1;
                b[nb * 2][1]     = r2; b[nb * 2 + 1][1] = r3;
            }
        };

        load_frag(0, afrag[0], bfrag[0]);
        #pragma unroll
        for (int kk = 0; kk < 4; kk++) {
            int cur = kk & 1, nxt = cur ^ 1;
            if (kk < 3) load_frag(kk + 1, afrag[nxt], bfrag[nxt]);
            #pragma unroll
            for (int mt = 0; mt < 4; mt++)
                #pragma unroll
                for (int nt = 0; nt < 8; nt++) {
                    asm volatile("mma.sync.aligned.m16n8k16.row.col.f32.f16.f16.f32 "
                        "{%0,%1,%2,%3}, {%4,%5,%6,%7}, {%8,%9}, {%0,%1,%2,%3};\n"
                        : "+f"(acc[mt][nt][0]), "+f"(acc[mt][nt][1]),
                          "+f"(acc[mt][nt][2]), "+f"(acc[mt][nt][3])
                        : "r"(afrag[cur][mt][0]), "r"(afrag[cur][mt][1]),
                          "r"(afrag[cur][mt][2]), "r"(afrag[cur][mt][3]),
                          "r"(bfrag[cur][nt][0]), "r"(bfrag[cur][nt][1]));
                }
        }
    }

    // epilogue: add bias, write fp32 hidden
    #pragma unroll
    for (int mt = 0; mt < 4; mt++) {
        int row0 = bm * BM + wm * 64 + mt * 16 + (lane >> 2);
        #pragma unroll
        for (int nt = 0; nt < 8; nt++) {
            int col = bn * BN + wn * 64 + nt * 8 + (lane & 3) * 2;
            float b0 = bias[col], b1 = bias[col + 1];
            float* p0 = g_hidden + (size_t)row0 * GV + col;
            float* p1 = g_hidden + (size_t)(row0 + 8) * GV + col;
            p0[0] = acc[mt][nt][0] + b0;
            p0[1] = acc[mt][nt][1] + b1;
            p1[0] = acc[mt][nt][2] + b0;
            p1[1] = acc[mt][nt][3] + b1;
        }
    }
}

// ---------------- row kernel: gumbel softmax + argmax + codevectors + soft-Z ----------------
// Warp-coalesced access (v = i*256 + t). Hybrid gumbel inner log:
// MUFU for u < 0.875 (absolute gumbel error <= 1.3e-6), 7-FMA log1p Taylor
// for u >= 0.875 (f = u-1 exact, |f| <= 0.125). Shuffle-based reductions.
__global__ void __launch_bounds__(256) row_kernel(
    const float* __restrict__ u, const float* __restrict__ emb,
    const int* __restrict__ mask, float* __restrict__ out)
{
    int r  = blockIdx.x;         // 0..8191 (= bt*2 + g)
    int bt = r >> 1, g = r & 1;
    int t  = threadIdx.x;
    int warp = t >> 5, lane = t & 31;
    const float* hrow = g_hidden + (size_t)bt * GV + (size_t)g * V_DIM;
    const float* urow = u + (size_t)r * V_DIM;
    const float* erow = emb + (size_t)g * V_DIM * DG;

    float h[32], y[32];
    float mh = -1e30f, my = -1e30f;
    int   bi = 0;
    #pragma unroll
    for (int i = 0; i < 32; i++) {
        int v = i * 256 + t;
        float hv = hrow[v];
        float uu = fmaxf(urow[v], 1.17549435e-38f);
        // inner = -log(uu), hybrid
        float inner_m = -__logf(uu);
        float f = uu - 1.0f;                       // exact for uu >= 0.5
        float q = fmaf(f, -0.125f, 0.14285714f);   // log1p Taylor, deg 7
        q = fmaf(q, f, -0.16666667f);
        q = fmaf(q, f,  0.20f);
        q = fmaf(q, f, -0.25f);
        q = fmaf(q, f,  0.33333333f);
        q = fmaf(q, f, -0.5f);
        q = fmaf(q, f,  1.0f);
        float inner_p = -(f * q);
        float inner = (uu >= 0.875f) ? inner_p : inner_m;
        float gum   = -__logf(inner);              // absolute accuracy suffices
        float yv = hv + gum;
        h[i] = hv; y[i] = yv;
        mh = fmaxf(mh, hv);
        if (yv > my) { my = yv; bi = v; }
    }

    // warp-level reduce: max h, argmax y
    #pragma unroll
    for (int o = 16; o; o >>= 1) {
        mh = fmaxf(mh, __shfl_xor_sync(0xffffffffu, mh, o));
        float omy = __shfl_xor_sync(0xffffffffu, my, o);
        int   obi = __shfl_xor_sync(0xffffffffu, bi, o);
        if (omy > my || (omy == my && obi < bi)) { my = omy; bi = obi; }
    }
    __shared__ float smh[8], smy[8], ssh[8], ssy[8];
    __shared__ int   sbi2[8];
    __shared__ float bcast[4];
    __shared__ int   bcast_i[1];
    if (lane == 0) { smh[warp] = mh; smy[warp] = my; sbi2[warp] = bi; }
    __syncthreads();
    if (t < 32) {
        mh = (lane < 8) ? smh[lane] : -1e30f;
        my = (lane < 8) ? smy[lane] : -1e30f;
        bi = (lane < 8) ? sbi2[lane] : 0x7fffffff;
        #pragma unroll
        for (int o = 4; o; o >>= 1) {
            mh = fmaxf(mh, __shfl_xor_sync(0xffffffffu, mh, o));
            float omy = __shfl_xor_sync(0xffffffffu, my, o);
            int   obi = __shfl_xor_sync(0xffffffffu, bi, o);
            if (omy > my || (omy == my && obi < bi)) { my = omy; bi = obi; }
        }
        if (lane == 0) { bcast[0] = mh; bcast[1] = my; bcast_i[0] = bi; }
    }
    __syncthreads();
    mh = bcast[0]; my = bcast[1];
    int amax = bcast_i[0];

    // exp sums (joint reduction of sh, sy)
    float sh = 0.f, sy = 0.f;
    #pragma unroll
    for (int i = 0; i < 32; i++) {
        sh += __expf(h[i] - mh);
        float e = __expf(y[i] - my);
        y[i] = e; sy += e;
    }
    #pragma unroll
    for (int o = 16; o; o >>= 1) {
        sh += __shfl_xor_sync(0xffffffffu, sh, o);
        sy += __shfl_xor_sync(0xffffffffu, sy, o);
    }
    if (lane == 0) { ssh[warp] = sh; ssy[warp] = sy; }
    __syncthreads();
    if (t < 32) {
        sh = (lane < 8) ? ssh[lane] : 0.f;
        sy = (lane < 8) ? ssy[lane] : 0.f;
        #pragma unroll
        for (int o = 4; o; o >>= 1) {
            sh += __shfl_xor_sync(0xffffffffu, sh, o);
            sy += __shfl_xor_sync(0xffffffffu, sy, o);
        }
        if (lane == 0) { bcast[2] = sh; bcast[3] = sy; }
    }
    __syncthreads();
    sh = bcast[2]; sy = bcast[3];

    // codevectors: cv[d] = sum_v p_v * emb[v][d]
    float cv[8] = {0,0,0,0,0,0,0,0};
    #pragma unroll
    for (int i = 0; i < 32; i++) {
        int v = i * 256 + t;
        const float4* ep = (const float4*)(erow + (size_t)v * DG);
        float4 e0 = ep[0], e1 = ep[1];
        float p = y[i];
        cv[0] = fmaf(p, e0.x, cv[0]); cv[1] = fmaf(p, e0.y, cv[1]);
        cv[2] = fmaf(p, e0.z, cv[2]); cv[3] = fmaf(p, e0.w, cv[3]);
        cv[4] = fmaf(p, e1.x, cv[4]); cv[5] = fmaf(p, e1.y, cv[5]);
        cv[6] = fmaf(p, e1.z, cv[6]); cv[7] = fmaf(p, e1.w, cv[7]);
    }
    #pragma unroll
    for (int d = 0; d < 8; d++)
        for (int o = 16; o; o >>= 1) cv[d] += __shfl_xor_sync(0xffffffffu, cv[d], o);

    __shared__ float scv[8][8];
    if (lane == 0) {
        #pragma unroll
        for (int d = 0; d < 8; d++) scv[warp][d] = cv[d];
    }
    __syncthreads();
    if (t < 8) {
        float s = 0.f;
        #pragma unroll
        for (int w = 0; w < 8; w++) s += scv[w][t];
        out[bt * 16 + g * 8 + t] = s / sy;
    }
    if (t == 0) {
        out[65537 + r] = (float)amax;                              // targets_idx
        g_R[r]  = mask[bt] ? (g_inv_msum / sh) : 0.f;
        g_MX[r] = mh;
    }
}

// ---------------- marginal column reduction ----------------
__global__ void __launch_bounds__(256) marg_kernel() {
    int c = blockIdx.x * 256 + threadIdx.x;   // 0..16383
    int g = c >> 13;
    int bt0 = blockIdx.y * 256;
    float acc = 0.f;
    for (int bt = bt0; bt < bt0 + 256; ++bt) {
        int r = bt * 2 + g;
        acc += g_R[r] * __expf(g_hidden[(size_t)bt * GV + c] - g_MX[r]);
    }
    atomicAdd(&g_marg[c], acc);
}

// ---------------- perplexity ----------------
__global__ void __launch_bounds__(256) final_kernel(float* __restrict__ out) {
    int t = threadIdx.x;
    float s0 = 0.f, s1v = 0.f;
    for (int c = t; c < V_DIM; c += 256) {
        float m = g_marg[c];
        s0 += m * my_logf(m + 1e-7f);
    }
    for (int c = V_DIM + t; c < GV; c += 256) {
        float m = g_marg[c];
        s1v += m * my_logf(m + 1e-7f);
    }
    __shared__ float sa[256], sb[256];
    sa[t] = s0; sb[t] = s1v; __syncthreads();
    for (int o = 128; o; o >>= 1) {
        if (t < o) { sa[t] += sa[t + o]; sb[t] += sb[t + o]; }
        __syncthreads();
    }
    if (t == 0) out[65536] = my_expf(-sa[0]) + my_expf(-sb[0]);
}

// ---------------- launch ----------------
extern "C" void kernel_launch(void* const* d_in, const int* in_sizes, int n_in,
                              void* d_out, int out_size) {
    const float* x    = (const float*)d_in[0];   // [8,512,256]
    const float* u    = (const float*)d_in[1];   // [8192, 8192]
    const float* emb  = (const float*)d_in[2];   // [1, 16384, 8]
    const float* W    = (const float*)d_in[3];   // [16384, 256]
    const float* bias = (const float*)d_in[4];   // [16384]
    const int*   mask = (const int*)d_in[5];     // [8,512]
    float* out = (float*)d_out;

    cudaFuncSetAttribute(gemm_kernel, cudaFuncAttributeMaxDynamicSharedMemorySize, GEMM_SMEM);

    prep_split_w<<<(GV * F_DIM + 255) / 256, 256>>>(W);
    prep_split_x<<<(BT_N * F_DIM + 255) / 256, 256>>>(x);
    prep_misc<<<1, 256>>>(mask);

    dim3 ggrid(GV / BN, BT_N / BM);   // (128, 32)
    gemm_kernel<<<ggrid, 128, GEMM_SMEM>>>(bias);

    row_kernel<<<BT_N * 2, 256>>>(u, emb, mask, out);

    dim3 mgrid(GV / 256, 16);
    marg_kernel<<<mgrid, 256>>>();

    final_kernel<<<1, 256>>>(out);
}

// round 7
// speedup vs baseline: 1.7833x; 1.0051x over previous
#include <cuda_runtime.h>
#include <cuda_fp16.h>
#include <cstdint>
#include <cstddef>

// ---------------- problem constants ----------------
#define BT_N   4096      // B*T
#define F_DIM  256
#define GV     16384     // G*V
#define V_DIM  8192
#define DG     8
#define KK     768       // 3 * F_DIM  (fp16-split GEMM packed along K)

// ---------------- scratch (device globals; no runtime allocation) ----------------
__device__ __half g_E[(size_t)BT_N * GV];               // 134 MB: exp(h) fp16 for marginal
__device__ float  g_part[(size_t)BT_N * 128 * 16];      // 33.5 MB per-(row,tile) partials
__device__ __half g_Asplit[(size_t)BT_N * KK];          // [xh | xh | xl]
__device__ __half g_Bsplit[(size_t)GV   * KK];          // [Wh | Wl | Wh]
__device__ float  g_R[BT_N * 2];                        // mask*inv_msum/Z per (bt,g)
__device__ float  g_marg[GV];                           // marginal accumulator
__device__ float  g_inv_msum;

// ---------------- FFMA log (for final kernel) + exp ----------------
__device__ __forceinline__ float my_logf(float a) {
    float m, r, s, t, i, f;
    int e;
    e = (__float_as_int(a) - 0x3f2aaaab) & 0xff800000;
    m = __int_as_float(__float_as_int(a) - e);
    i = (float)e * 1.19209290e-7f;
    f = m - 1.0f;
    s = f * f;
    r = -0.130310059f;
    t =  0.140869141f;
    r = fmaf(r, s, -0.121483512f);
    t = fmaf(t, s,  0.139814854f);
    r = fmaf(r, s, -0.166846126f);
    t = fmaf(t, s,  0.200120345f);
    r = fmaf(r, s, -0.249996200f);
    r = fmaf(t, f, r);
    r = fmaf(r, f,  0.333331972f);
    r = fmaf(r, f, -0.500000000f);
    r = fmaf(r, s, f);
    r = fmaf(i, 0.693147182f, r);
    return r;
}

__device__ __forceinline__ float my_expf(float a) {
    float f, r, j;
    int i;
    j = fmaf(1.442695041f, a, 12582912.f) - 12582912.f;
    f = fmaf(j, -6.93145752e-1f, a);
    f = fmaf(j, -1.42860677e-6f, f);
    i = (int)j;
    r = 1.37805939e-3f;
    r = fmaf(r, f, 8.37312452e-3f);
    r = fmaf(r, f, 4.16695364e-2f);
    r = fmaf(r, f, 1.66664720e-1f);
    r = fmaf(r, f, 4.99999851e-1f);
    r = fmaf(r, f, 1.00000000e+0f);
    r = fmaf(r, f, 1.00000000e+0f);
    r = __int_as_float(__float_as_int(r) + (i << 23));
    return r;
}

// gumbel = -log(-log(u)); hybrid: MUFU for u<0.875 (abs err ok), exact-f Taylor near 1
__device__ __forceinline__ float gumbel_from_u(float uu) {
    uu = fmaxf(uu, 1.17549435e-38f);
    float inner_m = -__logf(uu);
    float f = uu - 1.0f;                       // exact for uu >= 0.5 (Sterbenz)
    float q = fmaf(f, -0.125f, 0.14285714f);   // log1p Taylor deg 7
    q = fmaf(q, f, -0.16666667f);
    q = fmaf(q, f,  0.20f);
    q = fmaf(q, f, -0.25f);
    q = fmaf(q, f,  0.33333333f);
    q = fmaf(q, f, -0.5f);
    q = fmaf(q, f,  1.0f);
    float inner_p = -(f * q);
    float inner = (uu >= 0.875f) ? inner_p : inner_m;
    return -__logf(inner);
}

// ---------------- prep kernels ----------------
__global__ void prep_split_w(const float* __restrict__ W) {
    int idx = blockIdx.x * blockDim.x + threadIdx.x;
    if (idx >= GV * F_DIM) return;
    int n = idx >> 8, k = idx & 255;
    float w = W[idx];
    __half hi = __float2half_rn(w);
    __half lo = __float2half_rn(w - __half2float(hi));
    size_t base = (size_t)n * KK;
    g_Bsplit[base + k]        = hi;
    g_Bsplit[base + 256 + k]  = lo;
    g_Bsplit[base + 512 + k]  = hi;
}

__global__ void prep_split_x(const float* __restrict__ X) {
    int idx = blockIdx.x * blockDim.x + threadIdx.x;
    if (idx >= BT_N * F_DIM) return;
    int n = idx >> 8, k = idx & 255;
    float x = X[idx];
    __half hi = __float2half_rn(x);
    __half lo = __float2half_rn(x - __half2float(hi));
    size_t base = (size_t)n * KK;
    g_Asplit[base + k]        = hi;
    g_Asplit[base + 256 + k]  = hi;
    g_Asplit[base + 512 + k]  = lo;
}

__global__ void prep_misc(const int* __restrict__ mask) {
    int t = threadIdx.x;
    for (int i = t; i < GV; i += 256) g_marg[i] = 0.f;
    int s = 0;
    for (int i = t; i < BT_N; i += 256) s += mask[i];
    __shared__ int sm[256];
    sm[t] = s; __syncthreads();
    for (int o = 128; o; o >>= 1) { if (t < o) sm[t] += sm[t + o]; __syncthreads(); }
    if (t == 0) g_inv_msum = 1.0f / (float)sm[0];
}

// ---------------- fused GEMM + gumbel/softmax-partials epilogue ----------------
// Block tile 128x128, 4 warps, warp tile 64x64, BK=64, 3 stages, 2 CTAs/SM.
// Epilogue: h tile -> exp(h) fp16 store + y=h+gumbel into smem; per-row partials
// {sy, max y, argmax, Z, cv[8]} written to g_part. hidden never materialized.
#define BM 128
#define BN 128
#define BK 64
#define STAGES 3
#define A_BYTES  (BM * BK * 2)          // 16384
#define STG_BYTES (2 * A_BYTES)         // 32768
#define GEMM_SMEM (STAGES * STG_BYTES)  // 98304
#define YSTRIDE 133

__global__ void __launch_bounds__(128, 2) gemm_kernel(
    const float* __restrict__ bias, const float* __restrict__ U,
    const float* __restrict__ emb)
{
    extern __shared__ __align__(128) char smem[];
    int tid  = threadIdx.x;
    int lane = tid & 31, warp = tid >> 5;
    int wm = warp >> 1, wn = warp & 1;        // 2 x 2 warp grid, warp tile 64x64
    int bm = blockIdx.y, bn = blockIdx.x;
    const __half* gA = g_Asplit + (size_t)bm * BM * KK;
    const __half* gB = g_Bsplit + (size_t)bn * BN * KK;

    auto load_stage = [&](int s, int kt) {
        int k0 = kt * BK;
        char* sa = smem + s * STG_BYTES;
        char* sb = sa + A_BYTES;
        #pragma unroll
        for (int i = 0; i < 8; i++) {
            int idx = tid + 128 * i;       // 0..1023
            int row = idx >> 3, c16 = idx & 7;
            int pc  = c16 ^ (row & 7);
            uint32_t da = (uint32_t)__cvta_generic_to_shared(sa + row * 128 + pc * 16);
            asm volatile("cp.async.cg.shared.global [%0], [%1], 16;\n"
                :: "r"(da), "l"(gA + (size_t)row * KK + k0 + c16 * 8));
            uint32_t db = (uint32_t)__cvta_generic_to_shared(sb + row * 128 + pc * 16);
            asm volatile("cp.async.cg.shared.global [%0], [%1], 16;\n"
                :: "r"(db), "l"(gB + (size_t)row * KK + k0 + c16 * 8));
        }
    };

    float acc[4][8][4];
    #pragma unroll
    for (int a = 0; a < 4; a++)
        #pragma unroll
        for (int b = 0; b < 8; b++)
            #pragma unroll
            for (int c = 0; c < 4; c++) acc[a][b][c] = 0.f;

    const int NKT = KK / BK;  // 12
    #pragma unroll
    for (int kt = 0; kt < STAGES - 1; kt++) {
        load_stage(kt, kt);
        asm volatile("cp.async.commit_group;\n");
    }

    #pragma unroll 1
    for (int kt = 0; kt < NKT; kt++) {
        asm volatile("cp.async.wait_group 1;\n");
        __syncthreads();
        int pf = kt + STAGES - 1;
        if (pf < NKT) load_stage(pf % STAGES, pf);
        asm volatile("cp.async.commit_group;\n");

        int s = kt % STAGES;
        const char* sa = smem + s * STG_BYTES;
        const char* sb = sa + A_BYTES;
        #pragma unroll
        for (int kk = 0; kk < 4; kk++) {
            uint32_t a[4][4], b[8][2];
            int c16 = kk * 2 + (lane >> 4);
            #pragma unroll
            for (int mt = 0; mt < 4; mt++) {
                int row = wm * 64 + mt * 16 + (lane & 15);
                int pc  = c16 ^ (row & 7);
                uint32_t addr = (uint32_t)__cvta_generic_to_shared(sa + row * 128 + pc * 16);
                asm volatile("ldmatrix.sync.aligned.m8n8.x4.shared.b16 {%0,%1,%2,%3}, [%4];\n"
                    : "=r"(a[mt][0]), "=r"(a[mt][1]), "=r"(a[mt][2]), "=r"(a[mt][3]) : "r"(addr));
            }
            #pragma unroll
            for (int nb = 0; nb < 4; nb++) {
                int row = wn * 64 + nb * 16 + (lane & 15);
                int pc  = c16 ^ (row & 7);
                uint32_t addr = (uint32_t)__cvta_generic_to_shared(sb + row * 128 + pc * 16);
                uint32_t r0, r1, r2, r3;
                asm volatile("ldmatrix.sync.aligned.m8n8.x4.shared.b16 {%0,%1,%2,%3}, [%4];\n"
                    : "=r"(r0), "=r"(r1), "=r"(r2), "=r"(r3) : "r"(addr));
                b[nb * 2][0]     = r0; b[nb * 2 + 1][0] = r1;
                b[nb * 2][1]     = r2; b[nb * 2 + 1][1] = r3;
            }
            #pragma unroll
            for (int mt = 0; mt < 4; mt++)
                #pragma unroll
                for (int nt = 0; nt < 8; nt++) {
                    asm volatile("mma.sync.aligned.m16n8k16.row.col.f32.f16.f16.f32 "
                        "{%0,%1,%2,%3}, {%4,%5,%6,%7}, {%8,%9}, {%0,%1,%2,%3};\n"
                        : "+f"(acc[mt][nt][0]), "+f"(acc[mt][nt][1]),
                          "+f"(acc[mt][nt][2]), "+f"(acc[mt][nt][3])
                        : "r"(a[mt][0]), "r"(a[mt][1]), "r"(a[mt][2]), "r"(a[mt][3]),
                          "r"(b[nt][0]), "r"(b[nt][1]));
                }
        }
    }

    // ---- fused epilogue ----
    asm volatile("cp.async.wait_group 0;\n");
    __syncthreads();                                    // smem stages now reusable
    float* ysm  = (float*)smem;                         // [128][YSTRIDE]
    float* shsm = (float*)(smem + 128 * YSTRIDE * 4);   // [128][2]

    const int g  = bn >> 6;                             // codebook group of this tile
    const int v0 = (bn & 63) * 128;                     // first v of this tile

    // bias for this thread's 16 columns (constant across mt/ch)
    float2 bb[8];
    #pragma unroll
    for (int nt = 0; nt < 8; nt++) {
        int n = bn * BN + wn * 64 + nt * 8 + (lane & 3) * 2;
        bb[nt] = *(const float2*)(bias + n);
    }

    float shp[8];
    #pragma unroll
    for (int i = 0; i < 8; i++) shp[i] = 0.f;

    #pragma unroll
    for (int mt = 0; mt < 4; mt++) {
        #pragma unroll
        for (int ch = 0; ch < 2; ch++) {
            int row_l = wm * 64 + mt * 16 + (lane >> 2) + ch * 8;
            size_t mrow = (size_t)(bm * BM + row_l) * GV;
            #pragma unroll
            for (int nt = 0; nt < 8; nt++) {
                int col_l = wn * 64 + nt * 8 + (lane & 3) * 2;
                int n = bn * BN + col_l;
                float h0 = acc[mt][nt][ch * 2 + 0] + bb[nt].x;
                float h1 = acc[mt][nt][ch * 2 + 1] + bb[nt].y;
                float e0 = __expf(h0), e1 = __expf(h1);
                shp[mt * 2 + ch] += e0 + e1;
                *(__half2*)(&g_E[mrow + n]) = __floats2half2_rn(e0, e1);
                float2 uv = *(const float2*)(U + mrow + n);
                float y0 = h0 + gumbel_from_u(uv.x);
                float y1 = h1 + gumbel_from_u(uv.y);
                ysm[row_l * YSTRIDE + col_l]     = y0;
                ysm[row_l * YSTRIDE + col_l + 1] = y1;
            }
        }
    }
    // quad-reduce Z partials (4 lanes of each quad hold same row set)
    #pragma unroll
    for (int i = 0; i < 8; i++) {
        shp[i] += __shfl_xor_sync(0xffffffffu, shp[i], 1);
        shp[i] += __shfl_xor_sync(0xffffffffu, shp[i], 2);
    }
    if ((lane & 3) == 0) {
        #pragma unroll
        for (int i = 0; i < 8; i++) {
            int mt = i >> 1, ch = i & 1;
            int row_l = wm * 64 + mt * 16 + (lane >> 2) + ch * 8;
            shsm[row_l * 2 + wn] = shp[i];
        }
    }
    __syncthreads();

    // row phase: thread t owns row t (128 rows, 128 threads)
    {
        int row_l = tid;
        int m = bm * BM + row_l;
        float sh = shsm[row_l * 2 + 0] + shsm[row_l * 2 + 1];
        float sy = 0.f, myv = -1e30f;
        int bi = 0;
        float cv[8] = {0, 0, 0, 0, 0, 0, 0, 0};
        const float4* eb = (const float4*)(emb + ((size_t)g * V_DIM + v0) * DG);
        #pragma unroll 4
        for (int j = 0; j < 128; j++) {
            float yv = ysm[row_l * YSTRIDE + j];
            float ey = __expf(yv);           // no shift needed: y <= ~20
            sy += ey;
            float4 e0 = eb[j * 2], e1 = eb[j * 2 + 1];
            cv[0] = fmaf(ey, e0.x, cv[0]); cv[1] = fmaf(ey, e0.y, cv[1]);
            cv[2] = fmaf(ey, e0.z, cv[2]); cv[3] = fmaf(ey, e0.w, cv[3]);
            cv[4] = fmaf(ey, e1.x, cv[4]); cv[5] = fmaf(ey, e1.y, cv[5]);
            cv[6] = fmaf(ey, e1.z, cv[6]); cv[7] = fmaf(ey, e1.w, cv[7]);
            if (yv > myv) { myv = yv; bi = j; }   // strict > : first wins on tie
        }
        float* P = g_part + ((size_t)m * 128 + bn) * 16;
        ((float4*)P)[0] = make_float4(sy, myv, (float)(v0 + bi), sh);
        ((float4*)P)[1] = make_float4(cv[0], cv[1], cv[2], cv[3]);
        ((float4*)P)[2] = make_float4(cv[4], cv[5], cv[6], cv[7]);
    }
}

// ---------------- combine: reduce 64 tile-partials per (bt,g) ----------------
__global__ void __launch_bounds__(32) combine_kernel(
    const int* __restrict__ mask, float* __restrict__ out)
{
    int r = blockIdx.x;            // 0..8191
    int bt = r >> 1, gg = r & 1;
    int lane = threadIdx.x;
    const float* Pa = g_part + (((size_t)bt * 128) + gg * 64 + lane) * 16;
    const float* Pb = Pa + 32 * 16;
    float4 a0 = ((const float4*)Pa)[0], a1 = ((const float4*)Pa)[1], a2 = ((const float4*)Pa)[2];
    float4 b0 = ((const float4*)Pb)[0], b1 = ((const float4*)Pb)[1], b2 = ((const float4*)Pb)[2];
    float sy = a0.x + b0.x;
    float sh = a0.w + b0.w;
    float my = a0.y, vx = a0.z;
    if (b0.y > my || (b0.y == my && b0.z < vx)) { my = b0.y; vx = b0.z; }
    float cv[8];
    cv[0] = a1.x + b1.x; cv[1] = a1.y + b1.y; cv[2] = a1.z + b1.z; cv[3] = a1.w + b1.w;
    cv[4] = a2.x + b2.x; cv[5] = a2.y + b2.y; cv[6] = a2.z + b2.z; cv[7] = a2.w + b2.w;
    #pragma unroll
    for (int o = 16; o; o >>= 1) {
        sy += __shfl_xor_sync(0xffffffffu, sy, o);
        sh += __shfl_xor_sync(0xffffffffu, sh, o);
        float omy = __shfl_xor_sync(0xffffffffu, my, o);
        float ovx = __shfl_xor_sync(0xffffffffu, vx, o);
        if (omy > my || (omy == my && ovx < vx)) { my = omy; vx = ovx; }
        #pragma unroll
        for (int d = 0; d < 8; d++) cv[d] += __shfl_xor_sync(0xffffffffu, cv[d], o);
    }
    if (lane == 0) {
        float is = 1.f / sy;
        #pragma unroll
        for (int d = 0; d < 8; d++) out[bt * 16 + gg * 8 + d] = cv[d] * is;
        out[65537 + r] = vx;                                   // targets_idx
        g_R[r] = mask[bt] ? (g_inv_msum / sh) : 0.f;
    }
}

// ---------------- marginal column reduction (fp16 e) ----------------
__global__ void __launch_bounds__(256) marg_kernel() {
    int c = blockIdx.x * 256 + threadIdx.x;   // 0..16383
    int g = c >> 13;
    int bt0 = blockIdx.y * 256;
    float acc = 0.f;
    for (int bt = bt0; bt < bt0 + 256; ++bt) {
        acc += g_R[bt * 2 + g] * __half2float(g_E[(size_t)bt * GV + c]);
    }
    atomicAdd(&g_marg[c], acc);
}

// ---------------- perplexity ----------------
__global__ void __launch_bounds__(256) final_kernel(float* __restrict__ out) {
    int t = threadIdx.x;
    float s0 = 0.f, s1v = 0.f;
    for (int c = t; c < V_DIM; c += 256) {
        float m = g_marg[c];
        s0 += m * my_logf(m + 1e-7f);
    }
    for (int c = V_DIM + t; c < GV; c += 256) {
        float m = g_marg[c];
        s1v += m * my_logf(m + 1e-7f);
    }
    __shared__ float sa[256], sb[256];
    sa[t] = s0; sb[t] = s1v; __syncthreads();
    for (int o = 128; o; o >>= 1) {
        if (t < o) { sa[t] += sa[t + o]; sb[t] += sb[t + o]; }
        __syncthreads();
    }
    if (t == 0) out[65536] = my_expf(-sa[0]) + my_expf(-sb[0]);
}

// ---------------- launch ----------------
extern "C" void kernel_launch(void* const* d_in, const int* in_sizes, int n_in,
                              void* d_out, int out_size) {
    const float* x    = (const float*)d_in[0];   // [8,512,256]
    const float* u    = (const float*)d_in[1];   // [8192, 8192]
    const float* emb  = (const float*)d_in[2];   // [1, 16384, 8]
    const float* W    = (const float*)d_in[3];   // [16384, 256]
    const float* bias = (const float*)d_in[4];   // [16384]
    const int*   mask = (const int*)d_in[5];     // [8,512]
    float* out = (float*)d_out;

    cudaFuncSetAttribute(gemm_kernel, cudaFuncAttributeMaxDynamicSharedMemorySize, GEMM_SMEM);

    prep_split_w<<<(GV * F_DIM + 255) / 256, 256>>>(W);
    prep_split_x<<<(BT_N * F_DIM + 255) / 256, 256>>>(x);
    prep_misc<<<1, 256>>>(mask);

    dim3 ggrid(GV / BN, BT_N / BM);   // (128, 32)
    gemm_kernel<<<ggrid, 128, GEMM_SMEM>>>(bias, u, emb);

    combine_kernel<<<BT_N * 2, 32>>>(mask, out);

    dim3 mgrid(GV / 256, 16);
    marg_kernel<<<mgrid, 256>>>();

    final_kernel<<<1, 256>>>(out);
}

// round 8
// speedup vs baseline: 1.7929x; 1.0054x over previous
#include <cuda_runtime.h>
#include <cuda_fp16.h>
#include <cstdint>
#include <cstddef>

// ---------------- problem constants ----------------
#define BT_N   4096      // B*T
#define F_DIM  256
#define GV     16384     // G*V
#define V_DIM  8192
#define DG     8
#define KK     768       // 3 * F_DIM  (fp16-split GEMM packed along K)

// ---------------- scratch (device globals; no runtime allocation) ----------------
__device__ __half g_E[(size_t)BT_N * GV];               // 134 MB: exp(h) fp16 for marginal
__device__ float  g_part[(size_t)BT_N * 128 * 16];      // 33.5 MB per-(row,tile) partials
__device__ __half g_Asplit[(size_t)BT_N * KK];          // [xh | xh | xl]
__device__ __half g_Bsplit[(size_t)GV   * KK];          // [Wh | Wl | Wh]
__device__ float  g_R[BT_N * 2];                        // mask*inv_msum/Z per (bt,g)
__device__ float  g_marg[GV];                           // marginal accumulator
__device__ float  g_inv_msum;

// ---------------- FFMA log (final kernel) + exp ----------------
__device__ __forceinline__ float my_logf(float a) {
    float m, r, s, t, i, f;
    int e;
    e = (__float_as_int(a) - 0x3f2aaaab) & 0xff800000;
    m = __int_as_float(__float_as_int(a) - e);
    i = (float)e * 1.19209290e-7f;
    f = m - 1.0f;
    s = f * f;
    r = -0.130310059f;
    t =  0.140869141f;
    r = fmaf(r, s, -0.121483512f);
    t = fmaf(t, s,  0.139814854f);
    r = fmaf(r, s, -0.166846126f);
    t = fmaf(t, s,  0.200120345f);
    r = fmaf(r, s, -0.249996200f);
    r = fmaf(t, f, r);
    r = fmaf(r, f,  0.333331972f);
    r = fmaf(r, f, -0.500000000f);
    r = fmaf(r, s, f);
    r = fmaf(i, 0.693147182f, r);
    return r;
}

__device__ __forceinline__ float my_expf(float a) {
    float f, r, j;
    int i;
    j = fmaf(1.442695041f, a, 12582912.f) - 12582912.f;
    f = fmaf(j, -6.93145752e-1f, a);
    f = fmaf(j, -1.42860677e-6f, f);
    i = (int)j;
    r = 1.37805939e-3f;
    r = fmaf(r, f, 8.37312452e-3f);
    r = fmaf(r, f, 4.16695364e-2f);
    r = fmaf(r, f, 1.66664720e-1f);
    r = fmaf(r, f, 4.99999851e-1f);
    r = fmaf(r, f, 1.00000000e+0f);
    r = fmaf(r, f, 1.00000000e+0f);
    r = __int_as_float(__float_as_int(r) + (i << 23));
    return r;
}

// inner = -log(u); hybrid: MUFU for u<0.875 (inner>0.13, rel err ~2.3e-6),
// exact-f log1p Taylor for u>=0.875 (rel err ~6e-8 even as inner -> 0).
__device__ __forceinline__ float neg_log_u(float uu) {
    uu = fmaxf(uu, 1.17549435e-38f);
    float inner_m = -__logf(uu);
    float f = uu - 1.0f;                       // exact for uu >= 0.5 (Sterbenz)
    float q = fmaf(f, -0.125f, 0.14285714f);   // log1p Taylor deg 7
    q = fmaf(q, f, -0.16666667f);
    q = fmaf(q, f,  0.20f);
    q = fmaf(q, f, -0.25f);
    q = fmaf(q, f,  0.33333333f);
    q = fmaf(q, f, -0.5f);
    q = fmaf(q, f,  1.0f);
    float inner_p = -(f * q);
    return (uu >= 0.875f) ? inner_p : inner_m;
}

// ---------------- prep kernels ----------------
__global__ void prep_split_w(const float* __restrict__ W) {
    int idx = blockIdx.x * blockDim.x + threadIdx.x;
    if (idx >= GV * F_DIM) return;
    int n = idx >> 8, k = idx & 255;
    float w = W[idx];
    __half hi = __float2half_rn(w);
    __half lo = __float2half_rn(w - __half2float(hi));
    size_t base = (size_t)n * KK;
    g_Bsplit[base + k]        = hi;
    g_Bsplit[base + 256 + k]  = lo;
    g_Bsplit[base + 512 + k]  = hi;
}

__global__ void prep_split_x(const float* __restrict__ X) {
    int idx = blockIdx.x * blockDim.x + threadIdx.x;
    if (idx >= BT_N * F_DIM) return;
    int n = idx >> 8, k = idx & 255;
    float x = X[idx];
    __half hi = __float2half_rn(x);
    __half lo = __float2half_rn(x - __half2float(hi));
    size_t base = (size_t)n * KK;
    g_Asplit[base + k]        = hi;
    g_Asplit[base + 256 + k]  = hi;
    g_Asplit[base + 512 + k]  = lo;
}

__global__ void prep_misc(const int* __restrict__ mask) {
    int t = threadIdx.x;
    for (int i = t; i < GV; i += 256) g_marg[i] = 0.f;
    int s = 0;
    for (int i = t; i < BT_N; i += 256) s += mask[i];
    __shared__ int sm[256];
    sm[t] = s; __syncthreads();
    for (int o = 128; o; o >>= 1) { if (t < o) sm[t] += sm[t + o]; __syncthreads(); }
    if (t == 0) g_inv_msum = 1.0f / (float)sm[0];
}

// ---------------- fused GEMM + epilogue ----------------
// Block tile 128x128, 4 warps, warp tile 64x64, BK=64, 3 stages, 2 CTAs/SM.
// Epilogue v2: ey = exp(h)/(-log u) -- no outer log, no second exp.
#define BM 128
#define BN 128
#define BK 64
#define STAGES 3
#define A_BYTES  (BM * BK * 2)          // 16384
#define STG_BYTES (2 * A_BYTES)         // 32768
#define GEMM_SMEM (STAGES * STG_BYTES)  // 98304
#define YSTRIDE 133

__global__ void __launch_bounds__(128, 2) gemm_kernel(
    const float* __restrict__ bias, const float* __restrict__ U,
    const float* __restrict__ emb)
{
    extern __shared__ __align__(128) char smem[];
    int tid  = threadIdx.x;
    int lane = tid & 31, warp = tid >> 5;
    int wm = warp >> 1, wn = warp & 1;        // 2 x 2 warp grid, warp tile 64x64
    int bm = blockIdx.y, bn = blockIdx.x;
    const __half* gA = g_Asplit + (size_t)bm * BM * KK;
    const __half* gB = g_Bsplit + (size_t)bn * BN * KK;

    auto load_stage = [&](int s, int kt) {
        int k0 = kt * BK;
        char* sa = smem + s * STG_BYTES;
        char* sb = sa + A_BYTES;
        #pragma unroll
        for (int i = 0; i < 8; i++) {
            int idx = tid + 128 * i;       // 0..1023
            int row = idx >> 3, c16 = idx & 7;
            int pc  = c16 ^ (row & 7);
            uint32_t da = (uint32_t)__cvta_generic_to_shared(sa + row * 128 + pc * 16);
            asm volatile("cp.async.cg.shared.global [%0], [%1], 16;\n"
                :: "r"(da), "l"(gA + (size_t)row * KK + k0 + c16 * 8));
            uint32_t db = (uint32_t)__cvta_generic_to_shared(sb + row * 128 + pc * 16);
            asm volatile("cp.async.cg.shared.global [%0], [%1], 16;\n"
                :: "r"(db), "l"(gB + (size_t)row * KK + k0 + c16 * 8));
        }
    };

    float acc[4][8][4];
    #pragma unroll
    for (int a = 0; a < 4; a++)
        #pragma unroll
        for (int b = 0; b < 8; b++)
            #pragma unroll
            for (int c = 0; c < 4; c++) acc[a][b][c] = 0.f;

    const int NKT = KK / BK;  // 12
    #pragma unroll
    for (int kt = 0; kt < STAGES - 1; kt++) {
        load_stage(kt, kt);
        asm volatile("cp.async.commit_group;\n");
    }

    #pragma unroll 1
    for (int kt = 0; kt < NKT; kt++) {
        asm volatile("cp.async.wait_group 1;\n");
        __syncthreads();
        int pf = kt + STAGES - 1;
        if (pf < NKT) load_stage(pf % STAGES, pf);
        asm volatile("cp.async.commit_group;\n");

        int s = kt % STAGES;
        const char* sa = smem + s * STG_BYTES;
        const char* sb = sa + A_BYTES;
        #pragma unroll
        for (int kk = 0; kk < 4; kk++) {
            uint32_t a[4][4], b[8][2];
            int c16 = kk * 2 + (lane >> 4);
            #pragma unroll
            for (int mt = 0; mt < 4; mt++) {
                int row = wm * 64 + mt * 16 + (lane & 15);
                int pc  = c16 ^ (row & 7);
                uint32_t addr = (uint32_t)__cvta_generic_to_shared(sa + row * 128 + pc * 16);
                asm volatile("ldmatrix.sync.aligned.m8n8.x4.shared.b16 {%0,%1,%2,%3}, [%4];\n"
                    : "=r"(a[mt][0]), "=r"(a[mt][1]), "=r"(a[mt][2]), "=r"(a[mt][3]) : "r"(addr));
            }
            #pragma unroll
            for (int nb = 0; nb < 4; nb++) {
                int row = wn * 64 + nb * 16 + (lane & 15);
                int pc  = c16 ^ (row & 7);
                uint32_t addr = (uint32_t)__cvta_generic_to_shared(sb + row * 128 + pc * 16);
                uint32_t r0, r1, r2, r3;
                asm volatile("ldmatrix.sync.aligned.m8n8.x4.shared.b16 {%0,%1,%2,%3}, [%4];\n"
                    : "=r"(r0), "=r"(r1), "=r"(r2), "=r"(r3) : "r"(addr));
                b[nb * 2][0]     = r0; b[nb * 2 + 1][0] = r1;
                b[nb * 2][1]     = r2; b[nb * 2 + 1][1] = r3;
            }
            #pragma unroll
            for (int mt = 0; mt < 4; mt++)
                #pragma unroll
                for (int nt = 0; nt < 8; nt++) {
                    asm volatile("mma.sync.aligned.m16n8k16.row.col.f32.f16.f16.f32 "
                        "{%0,%1,%2,%3}, {%4,%5,%6,%7}, {%8,%9}, {%0,%1,%2,%3};\n"
                        : "+f"(acc[mt][nt][0]), "+f"(acc[mt][nt][1]),
                          "+f"(acc[mt][nt][2]), "+f"(acc[mt][nt][3])
                        : "r"(a[mt][0]), "r"(a[mt][1]), "r"(a[mt][2]), "r"(a[mt][3]),
                          "r"(b[nt][0]), "r"(b[nt][1]));
                }
        }
    }

    // ---- epilogue v2 ----
    asm volatile("cp.async.wait_group 0;\n");
    __syncthreads();                                    // smem stages reusable
    float* ysm  = (float*)smem;                         // [128][YSTRIDE] holds ey
    float* shsm = (float*)(smem + 128 * YSTRIDE * 4);   // [128][2]

    const int g  = bn >> 6;
    const int v0 = (bn & 63) * 128;

    float2 bb[8];
    #pragma unroll
    for (int nt = 0; nt < 8; nt++) {
        int n = bn * BN + wn * 64 + nt * 8 + (lane & 3) * 2;
        bb[nt] = *(const float2*)(bias + n);
    }

    float shp[8];
    #pragma unroll
    for (int i = 0; i < 8; i++) shp[i] = 0.f;

    #pragma unroll
    for (int mt = 0; mt < 4; mt++) {
        #pragma unroll
        for (int ch = 0; ch < 2; ch++) {
            int row_l = wm * 64 + mt * 16 + (lane >> 2) + ch * 8;
            size_t mrow = (size_t)(bm * BM + row_l) * GV;
            #pragma unroll
            for (int nt = 0; nt < 8; nt++) {
                int col_l = wn * 64 + nt * 8 + (lane & 3) * 2;
                int n = bn * BN + col_l;
                float h0 = acc[mt][nt][ch * 2 + 0] + bb[nt].x;
                float h1 = acc[mt][nt][ch * 2 + 1] + bb[nt].y;
                float e0 = __expf(h0), e1 = __expf(h1);
                shp[mt * 2 + ch] += e0 + e1;
                *(__half2*)(&g_E[mrow + n]) = __floats2half2_rn(e0, e1);
                float2 uv = *(const float2*)(U + mrow + n);
                // ey = exp(h + gumbel) = e / (-log u)
                float ey0 = __fdividef(e0, neg_log_u(uv.x));
                float ey1 = __fdividef(e1, neg_log_u(uv.y));
                ysm[row_l * YSTRIDE + col_l]     = ey0;
                ysm[row_l * YSTRIDE + col_l + 1] = ey1;
            }
        }
    }
    #pragma unroll
    for (int i = 0; i < 8; i++) {
        shp[i] += __shfl_xor_sync(0xffffffffu, shp[i], 1);
        shp[i] += __shfl_xor_sync(0xffffffffu, shp[i], 2);
    }
    if ((lane & 3) == 0) {
        #pragma unroll
        for (int i = 0; i < 8; i++) {
            int mt = i >> 1, ch = i & 1;
            int row_l = wm * 64 + mt * 16 + (lane >> 2) + ch * 8;
            shsm[row_l * 2 + wn] = shp[i];
        }
    }
    __syncthreads();

    // row phase: thread t owns row t; pure LDS + FMA + compares
    {
        int row_l = tid;
        int m = bm * BM + row_l;
        float sh = shsm[row_l * 2 + 0] + shsm[row_l * 2 + 1];
        float sy = 0.f, myv = -1e30f;
        int bi = 0;
        float cv[8] = {0, 0, 0, 0, 0, 0, 0, 0};
        const float4* eb = (const float4*)(emb + ((size_t)g * V_DIM + v0) * DG);
        #pragma unroll 4
        for (int j = 0; j < 128; j++) {
            float ey = ysm[row_l * YSTRIDE + j];
            sy += ey;
            float4 e0 = eb[j * 2], e1 = eb[j * 2 + 1];
            cv[0] = fmaf(ey, e0.x, cv[0]); cv[1] = fmaf(ey, e0.y, cv[1]);
            cv[2] = fmaf(ey, e0.z, cv[2]); cv[3] = fmaf(ey, e0.w, cv[3]);
            cv[4] = fmaf(ey, e1.x, cv[4]); cv[5] = fmaf(ey, e1.y, cv[5]);
            cv[6] = fmaf(ey, e1.z, cv[6]); cv[7] = fmaf(ey, e1.w, cv[7]);
            if (ey > myv) { myv = ey; bi = j; }   // monotone in y; first wins tie
        }
        float* P = g_part + ((size_t)m * 128 + bn) * 16;
        ((float4*)P)[0] = make_float4(sy, myv, (float)(v0 + bi), sh);
        ((float4*)P)[1] = make_float4(cv[0], cv[1], cv[2], cv[3]);
        ((float4*)P)[2] = make_float4(cv[4], cv[5], cv[6], cv[7]);
    }
}

// ---------------- combine: reduce 64 tile-partials per (bt,g) ----------------
__global__ void __launch_bounds__(32) combine_kernel(
    const int* __restrict__ mask, float* __restrict__ out)
{
    int r = blockIdx.x;            // 0..8191
    int bt = r >> 1, gg = r & 1;
    int lane = threadIdx.x;
    const float* Pa = g_part + (((size_t)bt * 128) + gg * 64 + lane) * 16;
    const float* Pb = Pa + 32 * 16;
    float4 a0 = ((const float4*)Pa)[0], a1 = ((const float4*)Pa)[1], a2 = ((const float4*)Pa)[2];
    float4 b0 = ((const float4*)Pb)[0], b1 = ((const float4*)Pb)[1], b2 = ((const float4*)Pb)[2];
    float sy = a0.x + b0.x;
    float sh = a0.w + b0.w;
    float my = a0.y, vx = a0.z;
    if (b0.y > my || (b0.y == my && b0.z < vx)) { my = b0.y; vx = b0.z; }
    float cv[8];
    cv[0] = a1.x + b1.x; cv[1] = a1.y + b1.y; cv[2] = a1.z + b1.z; cv[3] = a1.w + b1.w;
    cv[4] = a2.x + b2.x; cv[5] = a2.y + b2.y; cv[6] = a2.z + b2.z; cv[7] = a2.w + b2.w;
    #pragma unroll
    for (int o = 16; o; o >>= 1) {
        sy += __shfl_xor_sync(0xffffffffu, sy, o);
        sh += __shfl_xor_sync(0xffffffffu, sh, o);
        float omy = __shfl_xor_sync(0xffffffffu, my, o);
        float ovx = __shfl_xor_sync(0xffffffffu, vx, o);
        if (omy > my || (omy == my && ovx < vx)) { my = omy; vx = ovx; }
        #pragma unroll
        for (int d = 0; d < 8; d++) cv[d] += __shfl_xor_sync(0xffffffffu, cv[d], o);
    }
    if (lane == 0) {
        float is = 1.f / sy;
        #pragma unroll
        for (int d = 0; d < 8; d++) out[bt * 16 + gg * 8 + d] = cv[d] * is;
        out[65537 + r] = vx;                                   // targets_idx
        g_R[r] = mask[bt] ? (g_inv_msum / sh) : 0.f;
    }
}

// ---------------- marginal column reduction (fp16 e) ----------------
__global__ void __launch_bounds__(256) marg_kernel() {
    int c = blockIdx.x * 256 + threadIdx.x;   // 0..16383
    int g = c >> 13;
    int bt0 = blockIdx.y * 256;
    float acc = 0.f;
    for (int bt = bt0; bt < bt0 + 256; ++bt) {
        acc += g_R[bt * 2 + g] * __half2float(g_E[(size_t)bt * GV + c]);
    }
    atomicAdd(&g_marg[c], acc);
}

// ---------------- perplexity ----------------
__global__ void __launch_bounds__(256) final_kernel(float* __restrict__ out) {
    int t = threadIdx.x;
    float s0 = 0.f, s1v = 0.f;
    for (int c = t; c < V_DIM; c += 256) {
        float m = g_marg[c];
        s0 += m * my_logf(m + 1e-7f);
    }
    for (int c = V_DIM + t; c < GV; c += 256) {
        float m = g_marg[c];
        s1v += m * my_logf(m + 1e-7f);
    }
    __shared__ float sa[256], sb[256];
    sa[t] = s0; sb[t] = s1v; __syncthreads();
    for (int o = 128; o; o >>= 1) {
        if (t < o) { sa[t] += sa[t + o]; sb[t] += sb[t + o]; }
        __syncthreads();
    }
    if (t == 0) out[65536] = my_expf(-sa[0]) + my_expf(-sb[0]);
}

// ---------------- launch ----------------
extern "C" void kernel_launch(void* const* d_in, const int* in_sizes, int n_in,
                              void* d_out, int out_size) {
    const float* x    = (const float*)d_in[0];   // [8,512,256]
    const float* u    = (const float*)d_in[1];   // [8192, 8192]
    const float* emb  = (const float*)d_in[2];   // [1, 16384, 8]
    const float* W    = (const float*)d_in[3];   // [16384, 256]
    const float* bias = (const float*)d_in[4];   // [16384]
    const int*   mask = (const int*)d_in[5];     // [8,512]
    float* out = (float*)d_out;

    cudaFuncSetAttribute(gemm_kernel, cudaFuncAttributeMaxDynamicSharedMemorySize, GEMM_SMEM);

    prep_split_w<<<(GV * F_DIM + 255) / 256, 256>>>(W);
    prep_split_x<<<(BT_N * F_DIM + 255) / 256, 256>>>(x);
    prep_misc<<<1, 256>>>(mask);

    dim3 ggrid(GV / BN, BT_N / BM);   // (128, 32)
    gemm_kernel<<<ggrid, 128, GEMM_SMEM>>>(bias, u, emb);

    combine_kernel<<<BT_N * 2, 32>>>(mask, out);

    dim3 mgrid(GV / 256, 16);
    marg_kernel<<<mgrid, 256>>>();

    final_kernel<<<1, 256>>>(out);
}